// round 11
// baseline (speedup 1.0000x reference)
#include <cuda_runtime.h>
#include <cuda_fp16.h>
#include <cstdint>

#define N_NODES 100000
#define N_PAIRS 160000
#define N_EDGES 320000
#define HIDDEN  256
#define DEPTH   3

// ---------------- scratch (device globals; no runtime allocation) ----------------
__device__ float  g_H[(size_t)N_EDGES * HIDDEN];
__device__ float  g_Mv[(size_t)N_NODES * HIDDEN];
__device__ __half g_Wh[(size_t)DEPTH * HIDDEN * HIDDEN];
__device__ int    g_counts[N_NODES];   // zero at load; re-zeroed by final segsum
__device__ int    g_offs[N_NODES + 1];
__device__ int    g_cursor[N_NODES];
__device__ int    g_elist[N_EDGES];
__device__ int    g_bincl[128];
__device__ int    g_bflag[128];        // zero at load; re-zeroed by final segsum
__device__ int    g_done;              // zero at load; re-zeroed by final segsum

__device__ __forceinline__ int rev_of(int e) {
    int r = e + N_PAIRS;
    return (r >= N_EDGES) ? r - N_EDGES : r;
}

// ---------------- launch 0: H0 init + histogram + W->fp16 (merged) ----------------
__global__ void k_inithist(const float* __restrict__ V, const float* __restrict__ E,
                           const int* __restrict__ src, const float* __restrict__ W) {
    int b = blockIdx.x;
    if (b < 80000) {
        int i = b * 256 + threadIdx.x;      // over N_EDGES*64 float4s
        int e = i >> 6, c = i & 63;
        int s = src[e];
        float4 ev = __ldcs(&((const float4*)E)[(size_t)e * 64 + c]);
        float4 vv = ((const float4*)V)[(size_t)s * 64 + c];
        float4 o;
        o.x = ev.x + vv.x; o.y = ev.y + vv.y; o.z = ev.z + vv.z; o.w = ev.w + vv.w;
        __stcs(&((float4*)g_H)[(size_t)e * 64 + c], o);
    } else if (b < 81250) {
        int e = (b - 80000) * 256 + threadIdx.x;
        if (e < N_EDGES) atomicAdd(&g_counts[src[e]], 1);
    } else {
        int i = (b - 81250) * 256 + threadIdx.x;
        if (i < DEPTH * HIDDEN * HIDDEN / 4) {
            float4 w = ((const float4*)W)[i];
            __half2 p0 = __floats2half2_rn(w.x, w.y);
            __half2 p1 = __floats2half2_rn(w.z, w.w);
            *(__half2*)(g_Wh + (size_t)i * 4)     = p0;
            *(__half2*)(g_Wh + (size_t)i * 4 + 2) = p1;
        }
    }
}

// ---------------- launch 1: scan + grid barrier + fill (98 co-resident blocks) ----------------
__global__ void k_scanfill(const int* __restrict__ src) {
    __shared__ int s_wsum[32];
    __shared__ int s_prev;
    const int b = blockIdx.x;
    const int nb = gridDim.x;
    int i = b * 1024 + threadIdx.x;
    int v = (i < N_NODES) ? g_counts[i] : 0;
    int lane = threadIdx.x & 31, w = threadIdx.x >> 5;
    int sc = v;
    #pragma unroll
    for (int d = 1; d < 32; d <<= 1) {
        int t = __shfl_up_sync(0xffffffffu, sc, d);
        if (lane >= d) sc += t;
    }
    if (lane == 31) s_wsum[w] = sc;
    __syncthreads();
    if (w == 0) {
        int ws = s_wsum[lane];
        #pragma unroll
        for (int d = 1; d < 32; d <<= 1) {
            int t = __shfl_up_sync(0xffffffffu, ws, d);
            if (lane >= d) ws += t;
        }
        s_wsum[lane] = ws;
    }
    __syncthreads();
    int total = s_wsum[31];
    if (threadIdx.x == 0) {
        int prev = 0;
        if (b > 0) {
            while (atomicAdd(&g_bflag[b - 1], 0) == 0) {}
            prev = g_bincl[b - 1];
        }
        s_prev = prev;
        g_bincl[b] = prev + total;
        __threadfence();
        atomicExch(&g_bflag[b], 1);
        if (b == nb - 1) g_offs[N_NODES] = prev + total;
    }
    __syncthreads();
    int excl = sc - v + (w > 0 ? s_wsum[w - 1] : 0) + s_prev;
    if (i < N_NODES) {
        g_offs[i] = excl;
        g_cursor[i] = excl;
    }
    __syncthreads();
    if (threadIdx.x == 0) {
        __threadfence();
        atomicAdd(&g_done, 1);
        while (atomicAdd(&g_done, 0) < nb) {}
    }
    __syncthreads();
    for (int e = b * 1024 + threadIdx.x; e < N_EDGES; e += nb * 1024) {
        int pos = atomicAdd(&g_cursor[src[e]], 1);
        g_elist[pos] = e;
    }
}

// ---------------- segment sums via CSR: warp-per-node, edge loop unrolled x2 ----------------
template <bool RELU_REV>
__global__ void __launch_bounds__(256)
k_segsum(const float* __restrict__ H, float* __restrict__ out) {
    const int lane = threadIdx.x & 31;
    const int n = blockIdx.x * 8 + (threadIdx.x >> 5);
    if (!RELU_REV) {   // cleanup for next graph replay
        int gid = blockIdx.x * 256 + threadIdx.x;
        if (gid < N_NODES) g_counts[gid] = 0;
        if (gid < 128) g_bflag[gid] = 0;
        if (gid == 0) g_done = 0;
    }
    if (n >= N_NODES) return;
    const int beg = g_offs[n], end = g_offs[n + 1];
    float4 a0 = make_float4(0.f, 0.f, 0.f, 0.f);
    float4 a1 = make_float4(0.f, 0.f, 0.f, 0.f);
    int p = beg;
    for (; p + 2 <= end; p += 2) {
        int ea = g_elist[p], eb = g_elist[p + 1];
        if (RELU_REV) { ea = rev_of(ea); eb = rev_of(eb); }
        float4 x0 = __ldcs(&((const float4*)H)[(size_t)ea * 64 + lane]);
        float4 x1 = __ldcs(&((const float4*)H)[(size_t)ea * 64 + lane + 32]);
        float4 y0 = __ldcs(&((const float4*)H)[(size_t)eb * 64 + lane]);
        float4 y1 = __ldcs(&((const float4*)H)[(size_t)eb * 64 + lane + 32]);
        if (RELU_REV) {
            x0.x = fmaxf(x0.x, 0.f); x0.y = fmaxf(x0.y, 0.f); x0.z = fmaxf(x0.z, 0.f); x0.w = fmaxf(x0.w, 0.f);
            x1.x = fmaxf(x1.x, 0.f); x1.y = fmaxf(x1.y, 0.f); x1.z = fmaxf(x1.z, 0.f); x1.w = fmaxf(x1.w, 0.f);
            y0.x = fmaxf(y0.x, 0.f); y0.y = fmaxf(y0.y, 0.f); y0.z = fmaxf(y0.z, 0.f); y0.w = fmaxf(y0.w, 0.f);
            y1.x = fmaxf(y1.x, 0.f); y1.y = fmaxf(y1.y, 0.f); y1.z = fmaxf(y1.z, 0.f); y1.w = fmaxf(y1.w, 0.f);
        }
        a0.x += x0.x + y0.x; a0.y += x0.y + y0.y; a0.z += x0.z + y0.z; a0.w += x0.w + y0.w;
        a1.x += x1.x + y1.x; a1.y += x1.y + y1.y; a1.z += x1.z + y1.z; a1.w += x1.w + y1.w;
    }
    if (p < end) {
        int ea = g_elist[p];
        if (RELU_REV) ea = rev_of(ea);
        float4 x0 = __ldcs(&((const float4*)H)[(size_t)ea * 64 + lane]);
        float4 x1 = __ldcs(&((const float4*)H)[(size_t)ea * 64 + lane + 32]);
        if (RELU_REV) {
            x0.x = fmaxf(x0.x, 0.f); x0.y = fmaxf(x0.y, 0.f); x0.z = fmaxf(x0.z, 0.f); x0.w = fmaxf(x0.w, 0.f);
            x1.x = fmaxf(x1.x, 0.f); x1.y = fmaxf(x1.y, 0.f); x1.z = fmaxf(x1.z, 0.f); x1.w = fmaxf(x1.w, 0.f);
        }
        a0.x += x0.x; a0.y += x0.y; a0.z += x0.z; a0.w += x0.w;
        a1.x += x1.x; a1.y += x1.y; a1.z += x1.z; a1.w += x1.w;
    }
    ((float4*)out)[(size_t)n * 64 + lane] = a0;
    ((float4*)out)[(size_t)n * 64 + lane + 32] = a1;
}

// ---------------- fused fp16 GEMM: 512 threads, 16 warps, warp tile 16x64 ----------------
// Tile j rows: edges [32j,32j+32) U [160000+32j,+32); rev maps tile onto itself (row^32).
//   A[i,k] = fp16( sMv[i,k] - relu(sH[i^32,k]) );  residual sH folded into acc;
//   H_out = acc + b.  Same traffic & rings as the R10 winner, but 2x warps/SM
// (launch_bounds(512,2) -> 64 regs, 32 warps/SM) to cover the LDSM->MMA chains.
// Producers split: threads <256 stream Hin, >=256 gather Mv (one gptr each).

#define BM 64
#define BK 16
#define NST 6
#define A_SLOTB 2048                       // 64 rows x 32B
#define B_SLOTB 8192                       // 256 rows x 32B
#define H_SLOTB 4096                       // 64 rows x 64B
#define OFF_A 0
#define OFF_B (2 * A_SLOTB)                // 4096
#define OFF_H (OFF_B + NST * B_SLOTB)      // 53248
#define OFF_MV (OFF_H + NST * H_SLOTB)     // 77824
#define GEMM_SMEM (OFF_MV + NST * H_SLOTB) // 102400

#define LDSM_X4(r0, r1, r2, r3, addr) \
    asm volatile("ldmatrix.sync.aligned.m8n8.x4.shared.b16 {%0,%1,%2,%3}, [%4];" \
        : "=r"(r0), "=r"(r1), "=r"(r2), "=r"(r3) : "r"(addr))

__device__ __forceinline__ void mma_f16(float* d, const unsigned* a, const unsigned* b) {
    asm volatile(
        "mma.sync.aligned.m16n8k16.row.col.f32.f16.f16.f32 "
        "{%0,%1,%2,%3}, {%4,%5,%6,%7}, {%8,%9}, {%0,%1,%2,%3};\n"
        : "+f"(d[0]), "+f"(d[1]), "+f"(d[2]), "+f"(d[3])
        : "r"(a[0]), "r"(a[1]), "r"(a[2]), "r"(a[3]), "r"(b[0]), "r"(b[1]));
}

__global__ void __launch_bounds__(512, 2)
k_gemm(const float* __restrict__ Hin, const float* __restrict__ Mv,
       const int* __restrict__ src, const __half* __restrict__ Wl,
       const float* __restrict__ bl, float* __restrict__ Hout) {
    extern __shared__ char smc[];
    const uint32_t sbase = (uint32_t)__cvta_generic_to_shared(smc);

    const int t = threadIdx.x;
    const int j = blockIdx.x;
    const int e1 = j * 32;
    const int e2 = N_PAIRS + j * 32;

    const int lane = t & 31, wid = t >> 5;
    const int wm = wid >> 2, wn = wid & 3;     // warp tile: rows [wm*16,+16), cols [wn*64,+64)
    const int lr = lane >> 2, lc = lane & 3;

    uint64_t polF, polL;   // L2 policies: stream Hin, keep Mv
    asm("createpolicy.fractional.L2::evict_first.b64 %0, 1.0;" : "=l"(polF));
    asm("createpolicy.fractional.L2::evict_last.b64 %0, 1.0;" : "=l"(polL));

    float acc[8][4];
    #pragma unroll
    for (int ni = 0; ni < 8; ++ni)
        #pragma unroll
        for (int q = 0; q < 4; ++q) acc[ni][q] = 0.f;

    // H/Mv producers: 256 threads each; owner row = (t&255)>>2, 16B at float-cols ((t&255)&3)*4
    const int prow = (t & 255) >> 2;
    const int pc4 = (t & 3) * 4;
    const int pedge = (prow < 32) ? (e1 + prow) : (e2 + prow - 32);
    const float* gptr = (t < 256)
        ? (Hin + (size_t)pedge * HIDDEN + pc4)
        : (Mv + (size_t)src[pedge] * HIDDEN + pc4);
    const uint32_t pDst = sbase + ((t < 256) ? OFF_H : OFF_MV) + prow * 64 + pc4 * 4;
    const uint64_t pPol = (t < 256) ? polF : polL;

    // B producer: thread t -> row n = t>>1, chunk c = t&1 (swizzled 32B rows)
    const int bn = t >> 1, bc = t & 1;
    const uint32_t bDst = sbase + OFF_B + (uint32_t)(bn * 32 + ((bc ^ ((bn >> 2) & 1)) << 4));
    const __half* wp = Wl + (size_t)bn * HIDDEN + bc * 8;

    // A store: thread t -> row t>>3, float2 at float-cols (t&7)*2  (4B STS, swizzled)
    const int srow = t >> 3;
    const int sc2 = (t & 7) * 2;
    const uint32_t aSt = sbase + OFF_A
        + (uint32_t)(srow * 32 + (((sc2 >> 3) ^ ((srow >> 2) & 1)) << 4) + (sc2 & 7) * 2);

    // ldmatrix lane addresses
    const int tsel = lane >> 3, lrow2 = lane & 7;
    const int arw = wm * 16 + (tsel & 1) * 8 + lrow2;
    const uint32_t aLd = sbase + OFF_A
        + (uint32_t)(arw * 32 + (((tsel >> 1) ^ ((arw >> 2) & 1)) << 4));
    const int brw0 = wn * 64 + (tsel >> 1) * 8 + lrow2;
    const uint32_t bLd0 = sbase + OFF_B
        + (uint32_t)(brw0 * 32 + (((tsel & 1) ^ ((brw0 >> 2) & 1)) << 4));

    auto issue = [&](int kt) {
        const int slot = kt % NST;
        const int k0 = kt * BK;
        {   // B: 512 x 16B
            asm volatile("cp.async.cg.shared.global [%0], [%1], 16;\n"
                :: "r"(bDst + slot * B_SLOTB), "l"(wp + k0));
        }
        {   // H (t<256) or Mv (t>=256): 1 x 16B with L2 policy
            asm volatile("cp.async.cg.shared.global.L2::cache_hint [%0], [%1], 16, %2;\n"
                :: "r"(pDst + slot * H_SLOTB), "l"(gptr + k0), "l"(pPol));
        }
        asm volatile("cp.async.commit_group;\n");
    };

    auto storeA = [&](int kt) {
        const int slot = kt % NST;
        const float2 m = *(const float2*)(smc + OFF_MV + slot * H_SLOTB + srow * 64 + sc2 * 4);
        const float2 h = *(const float2*)(smc + OFF_H + slot * H_SLOTB + (srow ^ 32) * 64 + sc2 * 4);
        __half2 p = __floats2half2_rn(m.x - fmaxf(h.x, 0.f), m.y - fmaxf(h.y, 0.f));
        *(__half2*)((char*)smc + (aSt - sbase) + (kt & 1) * A_SLOTB) = p;
    };

    const int KT = HIDDEN / BK;  // 16

    issue(0); issue(1); issue(2); issue(3); issue(4);
    asm volatile("cp.async.wait_group 3;\n");
    __syncthreads();
    storeA(0);

    #pragma unroll
    for (int kt = 0; kt < KT; ++kt) {
        if (kt <= 11)      asm volatile("cp.async.wait_group 3;\n");
        else if (kt == 12) asm volatile("cp.async.wait_group 2;\n");
        else if (kt == 13) asm volatile("cp.async.wait_group 1;\n");
        else               asm volatile("cp.async.wait_group 0;\n");
        __syncthreads();

        if (kt + 1 < KT) storeA(kt + 1);

        const int slot = kt % NST;

        // residual: chunk kt holds cols [16kt,16kt+16) -> warp col wn == kt>>2
        if (wn == (kt >> 2)) {
            const float* h0 = (const float*)(smc + OFF_H + slot * H_SLOTB) + (wm * 16) * 16;
            #pragma unroll
            for (int q = 0; q < 2; ++q) {
                const int ni = (kt & 3) * 2 + q;
                const float* hp2 = h0 + lr * 16 + q * 8 + lc * 2;
                float2 v0 = *(const float2*)hp2;
                float2 v1 = *(const float2*)(hp2 + 8 * 16);
                acc[ni][0] += v0.x; acc[ni][1] += v0.y;
                acc[ni][2] += v1.x; acc[ni][3] += v1.y;
            }
        }

        // fragments via ldmatrix (A slot = kt&1, written last iteration)
        unsigned af[4];
        LDSM_X4(af[0], af[1], af[2], af[3], aLd + (kt & 1) * A_SLOTB);
        const uint32_t bS = bLd0 + slot * B_SLOTB;
        #pragma unroll
        for (int pp = 0; pp < 2; ++pp) {
            unsigned bf[2][4];
            LDSM_X4(bf[0][0], bf[0][1], bf[0][2], bf[0][3], bS + (2 * pp) * 16 * 32);
            LDSM_X4(bf[1][0], bf[1][1], bf[1][2], bf[1][3], bS + (2 * pp + 1) * 16 * 32);
            mma_f16(acc[4 * pp + 0], af, &bf[0][0]);
            mma_f16(acc[4 * pp + 1], af, &bf[0][2]);
            mma_f16(acc[4 * pp + 2], af, &bf[1][0]);
            mma_f16(acc[4 * pp + 3], af, &bf[1][2]);
        }

        if (kt + 5 < KT) issue(kt + 5);
    }

    // epilogue: H_out = acc + b (residual already folded), streaming stores
    const int r0 = wm * 16 + lr;
    const int r1 = r0 + 8;
    const int ge0 = (r0 < 32) ? (e1 + r0) : (e2 + r0 - 32);
    const int ge1 = (r1 < 32) ? (e1 + r1) : (e2 + r1 - 32);
    #pragma unroll
    for (int ni = 0; ni < 8; ++ni) {
        int c0 = wn * 64 + ni * 8 + lc * 2;
        float2 bb = *(const float2*)(bl + c0);
        float2 o0, o1;
        o0.x = bb.x + acc[ni][0];
        o0.y = bb.y + acc[ni][1];
        o1.x = bb.x + acc[ni][2];
        o1.y = bb.y + acc[ni][3];
        __stcs((float2*)(Hout + (size_t)ge0 * HIDDEN + c0), o0);
        __stcs((float2*)(Hout + (size_t)ge1 * HIDDEN + c0), o1);
    }
}

// ---------------- launch ----------------
extern "C" void kernel_launch(void* const* d_in, const int* in_sizes, int n_in,
                              void* d_out, int out_size) {
    const float* V = (const float*)d_in[0];
    const float* E = (const float*)d_in[1];
    const float* W = (const float*)d_in[2];
    const float* b = (const float*)d_in[3];
    const int* edge_index = (const int*)d_in[4];
    const int* src = edge_index;

    float* outV = (float*)d_out;
    float* outH = outV + (size_t)N_NODES * HIDDEN;

    float* gH = nullptr;
    float* gMv = nullptr;
    __half* gWh = nullptr;
    cudaGetSymbolAddress((void**)&gH, g_H);
    cudaGetSymbolAddress((void**)&gMv, g_Mv);
    cudaGetSymbolAddress((void**)&gWh, g_Wh);

    cudaFuncSetAttribute(k_gemm, cudaFuncAttributeMaxDynamicSharedMemorySize, GEMM_SMEM);

    // launches: inithist(0), scanfill(1), segsum(2), gemm(3) <- ncu captures idx 3
    k_inithist<<<81442, 256>>>(V, E, src, W);
    k_scanfill<<<98, 1024>>>(src);

    float* bufs[2] = {gH, outH};
    for (int l = 0; l < DEPTH; ++l) {
        const float* Hin = bufs[l & 1];
        float* Hout = bufs[(l + 1) & 1];
        k_segsum<true><<<12500, 256>>>(Hin, gMv);
        k_gemm<<<N_EDGES / BM, 512, GEMM_SMEM>>>(Hin, gMv, src,
                                                 gWh + (size_t)l * HIDDEN * HIDDEN,
                                                 b + (size_t)l * HIDDEN, Hout);
    }
    k_segsum<false><<<12500, 256>>>(outH, outV);
}

// round 15
// speedup vs baseline: 1.1020x; 1.1020x over previous
#include <cuda_runtime.h>
#include <cuda_fp16.h>
#include <cstdint>

#define N_NODES 100000
#define N_PAIRS 160000
#define N_EDGES 320000
#define HIDDEN  256
#define DEPTH   3

// ---------------- scratch (device globals; no runtime allocation) ----------------
__device__ float  g_H[(size_t)N_EDGES * HIDDEN];
__device__ float  g_Mv[(size_t)N_NODES * HIDDEN];
__device__ __half g_Wh[(size_t)DEPTH * HIDDEN * HIDDEN];
__device__ int    g_counts[N_NODES];   // zero at load; re-zeroed by final segsum
__device__ int    g_offs[N_NODES + 1];
__device__ int    g_cursor[N_NODES];
__device__ int    g_elist[N_EDGES];
__device__ int    g_bincl[128];
__device__ int    g_bflag[128];        // zero at load; re-zeroed by final segsum
__device__ int    g_done;              // zero at load; re-zeroed by final segsum

__device__ __forceinline__ int rev_of(int e) {
    int r = e + N_PAIRS;
    return (r >= N_EDGES) ? r - N_EDGES : r;
}

// ---------------- launch 0: H0 init + histogram + W->fp16 (merged) ----------------
__global__ void k_inithist(const float* __restrict__ V, const float* __restrict__ E,
                           const int* __restrict__ src, const float* __restrict__ W) {
    int b = blockIdx.x;
    if (b < 80000) {
        int i = b * 256 + threadIdx.x;      // over N_EDGES*64 float4s
        int e = i >> 6, c = i & 63;
        int s = src[e];
        float4 ev = __ldcs(&((const float4*)E)[(size_t)e * 64 + c]);
        float4 vv = ((const float4*)V)[(size_t)s * 64 + c];
        float4 o;
        o.x = ev.x + vv.x; o.y = ev.y + vv.y; o.z = ev.z + vv.z; o.w = ev.w + vv.w;
        __stcs(&((float4*)g_H)[(size_t)e * 64 + c], o);
    } else if (b < 81250) {
        int e = (b - 80000) * 256 + threadIdx.x;
        if (e < N_EDGES) atomicAdd(&g_counts[src[e]], 1);
    } else {
        int i = (b - 81250) * 256 + threadIdx.x;
        if (i < DEPTH * HIDDEN * HIDDEN / 4) {
            float4 w = ((const float4*)W)[i];
            __half2 p0 = __floats2half2_rn(w.x, w.y);
            __half2 p1 = __floats2half2_rn(w.z, w.w);
            *(__half2*)(g_Wh + (size_t)i * 4)     = p0;
            *(__half2*)(g_Wh + (size_t)i * 4 + 2) = p1;
        }
    }
}

// ---------------- launch 1: scan + grid barrier + fill (98 co-resident blocks) ----------------
__global__ void k_scanfill(const int* __restrict__ src) {
    __shared__ int s_wsum[32];
    __shared__ int s_prev;
    const int b = blockIdx.x;
    const int nb = gridDim.x;
    int i = b * 1024 + threadIdx.x;
    int v = (i < N_NODES) ? g_counts[i] : 0;
    int lane = threadIdx.x & 31, w = threadIdx.x >> 5;
    int sc = v;
    #pragma unroll
    for (int d = 1; d < 32; d <<= 1) {
        int t = __shfl_up_sync(0xffffffffu, sc, d);
        if (lane >= d) sc += t;
    }
    if (lane == 31) s_wsum[w] = sc;
    __syncthreads();
    if (w == 0) {
        int ws = s_wsum[lane];
        #pragma unroll
        for (int d = 1; d < 32; d <<= 1) {
            int t = __shfl_up_sync(0xffffffffu, ws, d);
            if (lane >= d) ws += t;
        }
        s_wsum[lane] = ws;
    }
    __syncthreads();
    int total = s_wsum[31];
    if (threadIdx.x == 0) {
        int prev = 0;
        if (b > 0) {
            while (atomicAdd(&g_bflag[b - 1], 0) == 0) {}
            prev = g_bincl[b - 1];
        }
        s_prev = prev;
        g_bincl[b] = prev + total;
        __threadfence();
        atomicExch(&g_bflag[b], 1);
        if (b == nb - 1) g_offs[N_NODES] = prev + total;
    }
    __syncthreads();
    int excl = sc - v + (w > 0 ? s_wsum[w - 1] : 0) + s_prev;
    if (i < N_NODES) {
        g_offs[i] = excl;
        g_cursor[i] = excl;
    }
    __syncthreads();
    if (threadIdx.x == 0) {
        __threadfence();
        atomicAdd(&g_done, 1);
        while (atomicAdd(&g_done, 0) < nb) {}
    }
    __syncthreads();
    for (int e = b * 1024 + threadIdx.x; e < N_EDGES; e += nb * 1024) {
        int pos = atomicAdd(&g_cursor[src[e]], 1);
        g_elist[pos] = e;
    }
}

// ---------------- segment sums via CSR: warp-per-node, edge loop unrolled x2 ----------------
template <bool RELU_REV>
__global__ void __launch_bounds__(256)
k_segsum(const float* __restrict__ H, float* __restrict__ out) {
    const int lane = threadIdx.x & 31;
    const int n = blockIdx.x * 8 + (threadIdx.x >> 5);
    if (!RELU_REV) {   // cleanup for next graph replay
        int gid = blockIdx.x * 256 + threadIdx.x;
        if (gid < N_NODES) g_counts[gid] = 0;
        if (gid < 128) g_bflag[gid] = 0;
        if (gid == 0) g_done = 0;
    }
    if (n >= N_NODES) return;
    const int beg = g_offs[n], end = g_offs[n + 1];
    float4 a0 = make_float4(0.f, 0.f, 0.f, 0.f);
    float4 a1 = make_float4(0.f, 0.f, 0.f, 0.f);
    int p = beg;
    for (; p + 2 <= end; p += 2) {
        int ea = g_elist[p], eb = g_elist[p + 1];
        if (RELU_REV) { ea = rev_of(ea); eb = rev_of(eb); }
        float4 x0 = __ldcs(&((const float4*)H)[(size_t)ea * 64 + lane]);
        float4 x1 = __ldcs(&((const float4*)H)[(size_t)ea * 64 + lane + 32]);
        float4 y0 = __ldcs(&((const float4*)H)[(size_t)eb * 64 + lane]);
        float4 y1 = __ldcs(&((const float4*)H)[(size_t)eb * 64 + lane + 32]);
        if (RELU_REV) {
            x0.x = fmaxf(x0.x, 0.f); x0.y = fmaxf(x0.y, 0.f); x0.z = fmaxf(x0.z, 0.f); x0.w = fmaxf(x0.w, 0.f);
            x1.x = fmaxf(x1.x, 0.f); x1.y = fmaxf(x1.y, 0.f); x1.z = fmaxf(x1.z, 0.f); x1.w = fmaxf(x1.w, 0.f);
            y0.x = fmaxf(y0.x, 0.f); y0.y = fmaxf(y0.y, 0.f); y0.z = fmaxf(y0.z, 0.f); y0.w = fmaxf(y0.w, 0.f);
            y1.x = fmaxf(y1.x, 0.f); y1.y = fmaxf(y1.y, 0.f); y1.z = fmaxf(y1.z, 0.f); y1.w = fmaxf(y1.w, 0.f);
        }
        a0.x += x0.x + y0.x; a0.y += x0.y + y0.y; a0.z += x0.z + y0.z; a0.w += x0.w + y0.w;
        a1.x += x1.x + y1.x; a1.y += x1.y + y1.y; a1.z += x1.z + y1.z; a1.w += x1.w + y1.w;
    }
    if (p < end) {
        int ea = g_elist[p];
        if (RELU_REV) ea = rev_of(ea);
        float4 x0 = __ldcs(&((const float4*)H)[(size_t)ea * 64 + lane]);
        float4 x1 = __ldcs(&((const float4*)H)[(size_t)ea * 64 + lane + 32]);
        if (RELU_REV) {
            x0.x = fmaxf(x0.x, 0.f); x0.y = fmaxf(x0.y, 0.f); x0.z = fmaxf(x0.z, 0.f); x0.w = fmaxf(x0.w, 0.f);
            x1.x = fmaxf(x1.x, 0.f); x1.y = fmaxf(x1.y, 0.f); x1.z = fmaxf(x1.z, 0.f); x1.w = fmaxf(x1.w, 0.f);
        }
        a0.x += x0.x; a0.y += x0.y; a0.z += x0.z; a0.w += x0.w;
        a1.x += x1.x; a1.y += x1.y; a1.z += x1.z; a1.w += x1.w;
    }
    ((float4*)out)[(size_t)n * 64 + lane] = a0;
    ((float4*)out)[(size_t)n * 64 + lane + 32] = a1;
}

// ---------------- fused fp16 GEMM: BK=32, R13 structure + race fix ----------------
// Tile j rows: edges [32j,32j+32) U [160000+32j,+32); rev maps tile onto itself (row^32).
//   A[i,k] = fp16( sMv[i,k] - relu(sH[i^32,k]) );  residual sH folded into acc;
//   H_out = acc + b.  Block 64x256, 8 warps (2x4), warp tile 32x64, 2 CTAs/SM.
// BK=32: 8 k-iterations. Rings NST=3, issue distance 3; wait_group 1 at top of
// iter kt guarantees group kt+1 complete (storeA(kt+1) reads it) — this is the
// one-token fix of R13's race (was wait_group 2 = only kt complete).
// A double-buffered (kt&1). A/B smem: 64B rows, chunk swizzle c ^= (row>>1)&3.
// H/Mv: 144B row stride. L2: Hin evict_first, Mv evict_last, Hout __stcs.

#define BM 64
#define BK 32
#define NST 3
#define A_SLOTB 4096                       // 64 rows x 64B
#define B_SLOTB 16384                      // 256 rows x 64B
#define H_ROWB 144
#define H_SLOTB (64 * H_ROWB)              // 9216
#define OFF_A 0
#define OFF_B (2 * A_SLOTB)                // 8192
#define OFF_H (OFF_B + NST * B_SLOTB)      // 57344
#define OFF_MV (OFF_H + NST * H_SLOTB)     // 84992
#define GEMM_SMEM (OFF_MV + NST * H_SLOTB) // 112640

#define LDSM_X4(r0, r1, r2, r3, addr) \
    asm volatile("ldmatrix.sync.aligned.m8n8.x4.shared.b16 {%0,%1,%2,%3}, [%4];" \
        : "=r"(r0), "=r"(r1), "=r"(r2), "=r"(r3) : "r"(addr))

__device__ __forceinline__ void mma_f16(float* d, const unsigned* a, const unsigned* b) {
    asm volatile(
        "mma.sync.aligned.m16n8k16.row.col.f32.f16.f16.f32 "
        "{%0,%1,%2,%3}, {%4,%5,%6,%7}, {%8,%9}, {%0,%1,%2,%3};\n"
        : "+f"(d[0]), "+f"(d[1]), "+f"(d[2]), "+f"(d[3])
        : "r"(a[0]), "r"(a[1]), "r"(a[2]), "r"(a[3]), "r"(b[0]), "r"(b[1]));
}

__global__ void __launch_bounds__(256, 2)
k_gemm(const float* __restrict__ Hin, const float* __restrict__ Mv,
       const int* __restrict__ src, const __half* __restrict__ Wl,
       const float* __restrict__ bl, float* __restrict__ Hout) {
    extern __shared__ char smc[];
    const uint32_t sbase = (uint32_t)__cvta_generic_to_shared(smc);

    const int t = threadIdx.x;
    const int j = blockIdx.x;
    const int e1 = j * 32;
    const int e2 = N_PAIRS + j * 32;

    const int lane = t & 31, wid = t >> 5;
    const int wm = wid >> 2, wn = wid & 3;
    const int lr = lane >> 2, lc = lane & 3;

    uint64_t polF, polL;   // L2 policies: stream Hin, keep Mv
    asm("createpolicy.fractional.L2::evict_first.b64 %0, 1.0;" : "=l"(polF));
    asm("createpolicy.fractional.L2::evict_last.b64 %0, 1.0;" : "=l"(polL));

    float acc[2][8][4];
    #pragma unroll
    for (int mi = 0; mi < 2; ++mi)
        #pragma unroll
        for (int ni = 0; ni < 8; ++ni)
            #pragma unroll
            for (int q = 0; q < 4; ++q) acc[mi][ni][q] = 0.f;

    // producers: thread t -> row t>>2, 32B (8 floats) at float-cols (t&3)*8 of each 32-col chunk
    const int arow = t >> 2;
    const int ac = t & 3;                    // col-group (8 floats)
    const int aedge = (arow < 32) ? (e1 + arow) : (e2 + arow - 32);
    const float* mp = Mv + (size_t)src[aedge] * HIDDEN + ac * 8;
    const float* hgp = Hin + (size_t)aedge * HIDDEN + ac * 8;
    const uint32_t hDst = sbase + OFF_H + arow * H_ROWB + ac * 32;
    const uint32_t mDst = sbase + OFF_MV + arow * H_ROWB + ac * 32;

    // A store: thread t -> row arow, chunk ac (16B of halves), swizzled 64B rows
    const uint32_t aSt = sbase + OFF_A
        + (uint32_t)(arow * 64 + ((ac ^ ((arow >> 1) & 3)) << 4));

    // B producer: thread t -> row n = (t>>2)+64i, chunk c = t&3; swizzle const across i
    const int bswz = ((t >> 3) & 3);
    const uint32_t bDst0 = sbase + OFF_B
        + (uint32_t)((t >> 2) * 64 + (((t & 3) ^ bswz) << 4));
    const __half* wp0 = Wl + (size_t)(t >> 2) * HIDDEN + (t & 3) * 8;

    // ldmatrix lane addresses (64B swizzled rows)
    const int tsel = lane >> 3, lrow2 = lane & 7;
    const int arw = wm * 32 + (tsel & 1) * 8 + lrow2;
    const uint32_t aLd0 = sbase + OFF_A
        + (uint32_t)(arw * 64 + (((tsel >> 1) ^ ((arw >> 1) & 3)) << 4));
    const int brw0 = wn * 64 + (tsel >> 1) * 8 + lrow2;
    const uint32_t bLd0 = sbase + OFF_B
        + (uint32_t)(brw0 * 64 + (((tsel & 1) ^ ((brw0 >> 1) & 3)) << 4));

    auto issue = [&](int kt) {
        const int slot = kt % NST;
        const int k0 = kt * BK;
        #pragma unroll
        for (int i = 0; i < 4; ++i) {   // B: 1024 16B copies, 4/thread
            uint32_t dst = bDst0 + slot * B_SLOTB + i * 4096;
            const __half* sp = wp0 + (size_t)i * 64 * HIDDEN + k0;
            asm volatile("cp.async.cg.shared.global [%0], [%1], 16;\n" :: "r"(dst), "l"(sp));
        }
        {   // Hin: 2 x 16B / thread, streaming (evict_first)
            asm volatile("cp.async.cg.shared.global.L2::cache_hint [%0], [%1], 16, %2;\n"
                :: "r"(hDst + slot * H_SLOTB), "l"(hgp + k0), "l"(polF));
            asm volatile("cp.async.cg.shared.global.L2::cache_hint [%0], [%1], 16, %2;\n"
                :: "r"(hDst + slot * H_SLOTB + 16), "l"(hgp + k0 + 4), "l"(polF));
        }
        {   // Mv: 2 x 16B / thread (gathered), keep resident (evict_last)
            asm volatile("cp.async.cg.shared.global.L2::cache_hint [%0], [%1], 16, %2;\n"
                :: "r"(mDst + slot * H_SLOTB), "l"(mp + k0), "l"(polL));
            asm volatile("cp.async.cg.shared.global.L2::cache_hint [%0], [%1], 16, %2;\n"
                :: "r"(mDst + slot * H_SLOTB + 16), "l"(mp + k0 + 4), "l"(polL));
        }
        asm volatile("cp.async.commit_group;\n");
    };

    auto storeA = [&](int kt) {
        const int slot = kt % NST;
        const float4 m0 = *(const float4*)(smc + OFF_MV + slot * H_SLOTB + arow * H_ROWB + ac * 32);
        const float4 m1 = *(const float4*)(smc + OFF_MV + slot * H_SLOTB + arow * H_ROWB + ac * 32 + 16);
        const float4 h0 = *(const float4*)(smc + OFF_H + slot * H_SLOTB + (arow ^ 32) * H_ROWB + ac * 32);
        const float4 h1 = *(const float4*)(smc + OFF_H + slot * H_SLOTB + (arow ^ 32) * H_ROWB + ac * 32 + 16);
        __half2 a0 = __floats2half2_rn(m0.x - fmaxf(h0.x, 0.f), m0.y - fmaxf(h0.y, 0.f));
        __half2 a1 = __floats2half2_rn(m0.z - fmaxf(h0.z, 0.f), m0.w - fmaxf(h0.w, 0.f));
        __half2 a2 = __floats2half2_rn(m1.x - fmaxf(h1.x, 0.f), m1.y - fmaxf(h1.y, 0.f));
        __half2 a3 = __floats2half2_rn(m1.z - fmaxf(h1.z, 0.f), m1.w - fmaxf(h1.w, 0.f));
        uint4 pk;
        pk.x = *(uint32_t*)&a0; pk.y = *(uint32_t*)&a1;
        pk.z = *(uint32_t*)&a2; pk.w = *(uint32_t*)&a3;
        *(uint4*)((char*)smc + (aSt - sbase) + (kt & 1) * A_SLOTB) = pk;
    };

    const int KT = HIDDEN / BK;  // 8

    issue(0); issue(1); issue(2);
    asm volatile("cp.async.wait_group 2;\n");
    __syncthreads();
    storeA(0);

    #pragma unroll
    for (int kt = 0; kt < KT; ++kt) {
        // FIX vs R13: wait_group 1 (was 2) => group kt+1 complete before storeA(kt+1)
        if (kt <= 5) asm volatile("cp.async.wait_group 1;\n");
        else         asm volatile("cp.async.wait_group 0;\n");
        __syncthreads();

        if (kt + 1 < KT) storeA(kt + 1);

        const int slot = kt % NST;

        // residual: chunk kt holds cols [32kt,32kt+32) -> warp col wn == kt>>1
        if (wn == (kt >> 1)) {
            const int kl = kt & 1;
            const float* hb = (const float*)(smc + OFF_H + slot * H_SLOTB);
            #pragma unroll
            for (int mi = 0; mi < 2; ++mi) {
                const float* h0p = hb + (wm * 32 + mi * 16 + lr) * (H_ROWB / 4);
                #pragma unroll
                for (int q = 0; q < 4; ++q) {
                    const int ni = kl * 4 + q;
                    float2 v0 = *(const float2*)(h0p + q * 8 + lc * 2);
                    float2 v1 = *(const float2*)(h0p + 8 * (H_ROWB / 4) + q * 8 + lc * 2);
                    acc[mi][ni][0] += v0.x; acc[mi][ni][1] += v0.y;
                    acc[mi][ni][2] += v1.x; acc[mi][ni][3] += v1.y;
                }
            }
        }

        // fragments via ldmatrix; 2 k16-groups per iteration
        #pragma unroll
        for (int g = 0; g < 2; ++g) {
            unsigned af[2][4], bf[4][4];
            {
                const uint32_t aS = (aLd0 ^ (g << 5)) + (kt & 1) * A_SLOTB;
                LDSM_X4(af[0][0], af[0][1], af[0][2], af[0][3], aS);
                LDSM_X4(af[1][0], af[1][1], af[1][2], af[1][3], aS + 16 * 64);
            }
            {
                const uint32_t bS = (bLd0 ^ (g << 5)) + slot * B_SLOTB;
                #pragma unroll
                for (int p = 0; p < 4; ++p)
                    LDSM_X4(bf[p][0], bf[p][1], bf[p][2], bf[p][3], bS + p * 16 * 64);
            }
            #pragma unroll
            for (int mi = 0; mi < 2; ++mi) {
                #pragma unroll
                for (int p = 0; p < 4; ++p) {
                    mma_f16(acc[mi][2 * p],     af[mi], &bf[p][0]);
                    mma_f16(acc[mi][2 * p + 1], af[mi], &bf[p][2]);
                }
            }
        }

        __syncthreads();
        if (kt + 3 < KT) issue(kt + 3);
    }

    // epilogue: H_out = acc + b (residual already folded), streaming stores
    float2 bb[8];
    #pragma unroll
    for (int ni = 0; ni < 8; ++ni)
        bb[ni] = *(const float2*)(bl + wn * 64 + ni * 8 + lc * 2);

    #pragma unroll
    for (int mi = 0; mi < 2; ++mi) {
        const int r0 = wm * 32 + mi * 16 + lr;
        const int r1 = r0 + 8;
        const int ge0 = (r0 < 32) ? (e1 + r0) : (e2 + r0 - 32);
        const int ge1 = (r1 < 32) ? (e1 + r1) : (e2 + r1 - 32);
        #pragma unroll
        for (int ni = 0; ni < 8; ++ni) {
            int c0 = wn * 64 + ni * 8 + lc * 2;
            float2 o0, o1;
            o0.x = bb[ni].x + acc[mi][ni][0];
            o0.y = bb[ni].y + acc[mi][ni][1];
            o1.x = bb[ni].x + acc[mi][ni][2];
            o1.y = bb[ni].y + acc[mi][ni][3];
            __stcs((float2*)(Hout + (size_t)ge0 * HIDDEN + c0), o0);
            __stcs((float2*)(Hout + (size_t)ge1 * HIDDEN + c0), o1);
        }
    }
}

// ---------------- launch ----------------
extern "C" void kernel_launch(void* const* d_in, const int* in_sizes, int n_in,
                              void* d_out, int out_size) {
    const float* V = (const float*)d_in[0];
    const float* E = (const float*)d_in[1];
    const float* W = (const float*)d_in[2];
    const float* b = (const float*)d_in[3];
    const int* edge_index = (const int*)d_in[4];
    const int* src = edge_index;

    float* outV = (float*)d_out;
    float* outH = outV + (size_t)N_NODES * HIDDEN;

    float* gH = nullptr;
    float* gMv = nullptr;
    __half* gWh = nullptr;
    cudaGetSymbolAddress((void**)&gH, g_H);
    cudaGetSymbolAddress((void**)&gMv, g_Mv);
    cudaGetSymbolAddress((void**)&gWh, g_Wh);

    cudaFuncSetAttribute(k_gemm, cudaFuncAttributeMaxDynamicSharedMemorySize, GEMM_SMEM);

    // launches: inithist(0), scanfill(1), segsum(2), gemm(3) <- ncu captures idx 3
    k_inithist<<<81442, 256>>>(V, E, src, W);
    k_scanfill<<<98, 1024>>>(src);

    float* bufs[2] = {gH, outH};
    for (int l = 0; l < DEPTH; ++l) {
        const float* Hin = bufs[l & 1];
        float* Hout = bufs[(l + 1) & 1];
        k_segsum<true><<<12500, 256>>>(Hin, gMv);
        k_gemm<<<N_EDGES / BM, 256, GEMM_SMEM>>>(Hin, gMv, src,
                                                 gWh + (size_t)l * HIDDEN * HIDDEN,
                                                 b + (size_t)l * HIDDEN, Hout);
    }
    k_segsum<false><<<12500, 256>>>(outH, outV);
}

// round 16
// speedup vs baseline: 1.1207x; 1.0170x over previous
#include <cuda_runtime.h>
#include <cuda_fp16.h>
#include <cstdint>

#define N_NODES 100000
#define N_PAIRS 160000
#define N_EDGES 320000
#define HIDDEN  256
#define DEPTH   3

// ---------------- scratch (device globals; no runtime allocation) ----------------
__device__ float  g_H[(size_t)N_EDGES * HIDDEN];
__device__ float  g_Mv[(size_t)N_NODES * HIDDEN];
__device__ __half g_Wh[(size_t)DEPTH * HIDDEN * HIDDEN];
__device__ int    g_counts[N_NODES];   // zero at load; re-zeroed by final segsum
__device__ int    g_offs[N_NODES + 1];
__device__ int    g_cursor[N_NODES];
__device__ int    g_elist[N_EDGES];
__device__ int    g_bincl[128];
__device__ int    g_bflag[128];        // zero at load; re-zeroed by final segsum
__device__ int    g_done;              // zero at load; re-zeroed by final segsum

__device__ __forceinline__ int rev_of(int e) {
    int r = e + N_PAIRS;
    return (r >= N_EDGES) ? r - N_EDGES : r;
}

// ---------------- launch 0: H0 init + histogram + W->fp16 (merged) ----------------
__global__ void k_inithist(const float* __restrict__ V, const float* __restrict__ E,
                           const int* __restrict__ src, const float* __restrict__ W) {
    int b = blockIdx.x;
    if (b < 80000) {
        int i = b * 256 + threadIdx.x;      // over N_EDGES*64 float4s
        int e = i >> 6, c = i & 63;
        int s = src[e];
        float4 ev = __ldcs(&((const float4*)E)[(size_t)e * 64 + c]);
        float4 vv = ((const float4*)V)[(size_t)s * 64 + c];
        float4 o;
        o.x = ev.x + vv.x; o.y = ev.y + vv.y; o.z = ev.z + vv.z; o.w = ev.w + vv.w;
        __stcs(&((float4*)g_H)[(size_t)e * 64 + c], o);
    } else if (b < 81250) {
        int e = (b - 80000) * 256 + threadIdx.x;
        if (e < N_EDGES) atomicAdd(&g_counts[src[e]], 1);
    } else {
        int i = (b - 81250) * 256 + threadIdx.x;
        if (i < DEPTH * HIDDEN * HIDDEN / 4) {
            float4 w = ((const float4*)W)[i];
            __half2 p0 = __floats2half2_rn(w.x, w.y);
            __half2 p1 = __floats2half2_rn(w.z, w.w);
            *(__half2*)(g_Wh + (size_t)i * 4)     = p0;
            *(__half2*)(g_Wh + (size_t)i * 4 + 2) = p1;
        }
    }
}

// ---------------- launch 1: scan + grid barrier + fill (98 co-resident blocks) ----------------
__global__ void k_scanfill(const int* __restrict__ src) {
    __shared__ int s_wsum[32];
    __shared__ int s_prev;
    const int b = blockIdx.x;
    const int nb = gridDim.x;
    int i = b * 1024 + threadIdx.x;
    int v = (i < N_NODES) ? g_counts[i] : 0;
    int lane = threadIdx.x & 31, w = threadIdx.x >> 5;
    int sc = v;
    #pragma unroll
    for (int d = 1; d < 32; d <<= 1) {
        int t = __shfl_up_sync(0xffffffffu, sc, d);
        if (lane >= d) sc += t;
    }
    if (lane == 31) s_wsum[w] = sc;
    __syncthreads();
    if (w == 0) {
        int ws = s_wsum[lane];
        #pragma unroll
        for (int d = 1; d < 32; d <<= 1) {
            int t = __shfl_up_sync(0xffffffffu, ws, d);
            if (lane >= d) ws += t;
        }
        s_wsum[lane] = ws;
    }
    __syncthreads();
    int total = s_wsum[31];
    if (threadIdx.x == 0) {
        int prev = 0;
        if (b > 0) {
            while (atomicAdd(&g_bflag[b - 1], 0) == 0) {}
            prev = g_bincl[b - 1];
        }
        s_prev = prev;
        g_bincl[b] = prev + total;
        __threadfence();
        atomicExch(&g_bflag[b], 1);
        if (b == nb - 1) g_offs[N_NODES] = prev + total;
    }
    __syncthreads();
    int excl = sc - v + (w > 0 ? s_wsum[w - 1] : 0) + s_prev;
    if (i < N_NODES) {
        g_offs[i] = excl;
        g_cursor[i] = excl;
    }
    __syncthreads();
    if (threadIdx.x == 0) {
        __threadfence();
        atomicAdd(&g_done, 1);
        while (atomicAdd(&g_done, 0) < nb) {}
    }
    __syncthreads();
    for (int e = b * 1024 + threadIdx.x; e < N_EDGES; e += nb * 1024) {
        int pos = atomicAdd(&g_cursor[src[e]], 1);
        g_elist[pos] = e;
    }
}

// ---------------- segment sums via CSR: warp-per-node, edge loop unrolled x4 ----------------
template <bool RELU_REV>
__device__ __forceinline__ void seg_acc(const float* __restrict__ H, int e, int lane,
                                        float4& a0, float4& a1) {
    float4 x0 = __ldcs(&((const float4*)H)[(size_t)e * 64 + lane]);
    float4 x1 = __ldcs(&((const float4*)H)[(size_t)e * 64 + lane + 32]);
    if (RELU_REV) {
        x0.x = fmaxf(x0.x, 0.f); x0.y = fmaxf(x0.y, 0.f); x0.z = fmaxf(x0.z, 0.f); x0.w = fmaxf(x0.w, 0.f);
        x1.x = fmaxf(x1.x, 0.f); x1.y = fmaxf(x1.y, 0.f); x1.z = fmaxf(x1.z, 0.f); x1.w = fmaxf(x1.w, 0.f);
    }
    a0.x += x0.x; a0.y += x0.y; a0.z += x0.z; a0.w += x0.w;
    a1.x += x1.x; a1.y += x1.y; a1.z += x1.z; a1.w += x1.w;
}

template <bool RELU_REV>
__global__ void __launch_bounds__(256)
k_segsum(const float* __restrict__ H, float* __restrict__ out) {
    const int lane = threadIdx.x & 31;
    const int n = blockIdx.x * 8 + (threadIdx.x >> 5);
    if (!RELU_REV) {   // cleanup for next graph replay
        int gid = blockIdx.x * 256 + threadIdx.x;
        if (gid < N_NODES) g_counts[gid] = 0;
        if (gid < 128) g_bflag[gid] = 0;
        if (gid == 0) g_done = 0;
    }
    if (n >= N_NODES) return;
    const int beg = g_offs[n], end = g_offs[n + 1];
    float4 a0 = make_float4(0.f, 0.f, 0.f, 0.f);
    float4 a1 = make_float4(0.f, 0.f, 0.f, 0.f);
    int p = beg;
    for (; p + 4 <= end; p += 4) {
        int e0 = g_elist[p],     eA = g_elist[p + 1];
        int e2 = g_elist[p + 2], e3 = g_elist[p + 3];
        if (RELU_REV) { e0 = rev_of(e0); eA = rev_of(eA); e2 = rev_of(e2); e3 = rev_of(e3); }
        seg_acc<RELU_REV>(H, e0, lane, a0, a1);
        seg_acc<RELU_REV>(H, eA, lane, a0, a1);
        seg_acc<RELU_REV>(H, e2, lane, a0, a1);
        seg_acc<RELU_REV>(H, e3, lane, a0, a1);
    }
    for (; p < end; ++p) {
        int e = g_elist[p];
        if (RELU_REV) e = rev_of(e);
        seg_acc<RELU_REV>(H, e, lane, a0, a1);
    }
    ((float4*)out)[(size_t)n * 64 + lane] = a0;
    ((float4*)out)[(size_t)n * 64 + lane + 32] = a1;
}

// ---------------- fused fp16 GEMM: BK=32, software-pipelined inner loop ----------------
// Tile j rows: edges [32j,32j+32) U [160000+32j,+32); rev maps tile onto itself (row^32).
//   A[i,k] = fp16( sMv[i,k] - relu(sH[i^32,k]) );  residual sH folded into acc;
//   H_out = acc + b.  Block 64x256, 8 warps (2x4), warp tile 32x64, 2 CTAs/SM.
// BK=32: 8 k-iterations. Rings NST=3, issue distance 3, wait_group 1 (group kt+1
// complete before storeA(kt+1)). Inner-loop order hides LDSM latency:
//   LDSM(g0) -> storeA(kt+1) -> MMA(g0) -> residual -> LDSM(g1) -> MMA(g1).
// A double-buffered. A/B smem: 64B rows, chunk swizzle c ^= (row>>1)&3.
// H/Mv: 144B row stride. L2: Hin evict_first, Mv evict_last, Hout __stcs.

#define BM 64
#define BK 32
#define NST 3
#define A_SLOTB 4096                       // 64 rows x 64B
#define B_SLOTB 16384                      // 256 rows x 64B
#define H_ROWB 144
#define H_SLOTB (64 * H_ROWB)              // 9216
#define OFF_A 0
#define OFF_B (2 * A_SLOTB)                // 8192
#define OFF_H (OFF_B + NST * B_SLOTB)      // 57344
#define OFF_MV (OFF_H + NST * H_SLOTB)     // 84992
#define GEMM_SMEM (OFF_MV + NST * H_SLOTB) // 112640

#define LDSM_X4(r0, r1, r2, r3, addr) \
    asm volatile("ldmatrix.sync.aligned.m8n8.x4.shared.b16 {%0,%1,%2,%3}, [%4];" \
        : "=r"(r0), "=r"(r1), "=r"(r2), "=r"(r3) : "r"(addr))

__device__ __forceinline__ void mma_f16(float* d, const unsigned* a, const unsigned* b) {
    asm volatile(
        "mma.sync.aligned.m16n8k16.row.col.f32.f16.f16.f32 "
        "{%0,%1,%2,%3}, {%4,%5,%6,%7}, {%8,%9}, {%0,%1,%2,%3};\n"
        : "+f"(d[0]), "+f"(d[1]), "+f"(d[2]), "+f"(d[3])
        : "r"(a[0]), "r"(a[1]), "r"(a[2]), "r"(a[3]), "r"(b[0]), "r"(b[1]));
}

__global__ void __launch_bounds__(256, 2)
k_gemm(const float* __restrict__ Hin, const float* __restrict__ Mv,
       const int* __restrict__ src, const __half* __restrict__ Wl,
       const float* __restrict__ bl, float* __restrict__ Hout) {
    extern __shared__ char smc[];
    const uint32_t sbase = (uint32_t)__cvta_generic_to_shared(smc);

    const int t = threadIdx.x;
    const int j = blockIdx.x;
    const int e1 = j * 32;
    const int e2 = N_PAIRS + j * 32;

    const int lane = t & 31, wid = t >> 5;
    const int wm = wid >> 2, wn = wid & 3;
    const int lr = lane >> 2, lc = lane & 3;

    uint64_t polF, polL;   // L2 policies: stream Hin, keep Mv
    asm("createpolicy.fractional.L2::evict_first.b64 %0, 1.0;" : "=l"(polF));
    asm("createpolicy.fractional.L2::evict_last.b64 %0, 1.0;" : "=l"(polL));

    float acc[2][8][4];
    #pragma unroll
    for (int mi = 0; mi < 2; ++mi)
        #pragma unroll
        for (int ni = 0; ni < 8; ++ni)
            #pragma unroll
            for (int q = 0; q < 4; ++q) acc[mi][ni][q] = 0.f;

    // producers: thread t -> row t>>2, 32B (8 floats) at float-cols (t&3)*8 of each 32-col chunk
    const int arow = t >> 2;
    const int ac = t & 3;                    // col-group (8 floats)
    const int aedge = (arow < 32) ? (e1 + arow) : (e2 + arow - 32);
    const float* mp = Mv + (size_t)src[aedge] * HIDDEN + ac * 8;
    const float* hgp = Hin + (size_t)aedge * HIDDEN + ac * 8;
    const uint32_t hDst = sbase + OFF_H + arow * H_ROWB + ac * 32;
    const uint32_t mDst = sbase + OFF_MV + arow * H_ROWB + ac * 32;

    // A store: thread t -> row arow, chunk ac (16B of halves), swizzled 64B rows
    const uint32_t aSt = sbase + OFF_A
        + (uint32_t)(arow * 64 + ((ac ^ ((arow >> 1) & 3)) << 4));

    // B producer: thread t -> row n = (t>>2)+64i, chunk c = t&3; swizzle const across i
    const int bswz = ((t >> 3) & 3);
    const uint32_t bDst0 = sbase + OFF_B
        + (uint32_t)((t >> 2) * 64 + (((t & 3) ^ bswz) << 4));
    const __half* wp0 = Wl + (size_t)(t >> 2) * HIDDEN + (t & 3) * 8;

    // ldmatrix lane addresses (64B swizzled rows)
    const int tsel = lane >> 3, lrow2 = lane & 7;
    const int arw = wm * 32 + (tsel & 1) * 8 + lrow2;
    const uint32_t aLd0 = sbase + OFF_A
        + (uint32_t)(arw * 64 + (((tsel >> 1) ^ ((arw >> 1) & 3)) << 4));
    const int brw0 = wn * 64 + (tsel >> 1) * 8 + lrow2;
    const uint32_t bLd0 = sbase + OFF_B
        + (uint32_t)(brw0 * 64 + (((tsel & 1) ^ ((brw0 >> 1) & 3)) << 4));

    auto issue = [&](int kt) {
        const int slot = kt % NST;
        const int k0 = kt * BK;
        #pragma unroll
        for (int i = 0; i < 4; ++i) {   // B: 1024 16B copies, 4/thread
            uint32_t dst = bDst0 + slot * B_SLOTB + i * 4096;
            const __half* sp = wp0 + (size_t)i * 64 * HIDDEN + k0;
            asm volatile("cp.async.cg.shared.global [%0], [%1], 16;\n" :: "r"(dst), "l"(sp));
        }
        {   // Hin: 2 x 16B / thread, streaming (evict_first)
            asm volatile("cp.async.cg.shared.global.L2::cache_hint [%0], [%1], 16, %2;\n"
                :: "r"(hDst + slot * H_SLOTB), "l"(hgp + k0), "l"(polF));
            asm volatile("cp.async.cg.shared.global.L2::cache_hint [%0], [%1], 16, %2;\n"
                :: "r"(hDst + slot * H_SLOTB + 16), "l"(hgp + k0 + 4), "l"(polF));
        }
        {   // Mv: 2 x 16B / thread (gathered), keep resident (evict_last)
            asm volatile("cp.async.cg.shared.global.L2::cache_hint [%0], [%1], 16, %2;\n"
                :: "r"(mDst + slot * H_SLOTB), "l"(mp + k0), "l"(polL));
            asm volatile("cp.async.cg.shared.global.L2::cache_hint [%0], [%1], 16, %2;\n"
                :: "r"(mDst + slot * H_SLOTB + 16), "l"(mp + k0 + 4), "l"(polL));
        }
        asm volatile("cp.async.commit_group;\n");
    };

    auto storeA = [&](int kt) {
        const int slot = kt % NST;
        const float4 m0 = *(const float4*)(smc + OFF_MV + slot * H_SLOTB + arow * H_ROWB + ac * 32);
        const float4 m1 = *(const float4*)(smc + OFF_MV + slot * H_SLOTB + arow * H_ROWB + ac * 32 + 16);
        const float4 h0 = *(const float4*)(smc + OFF_H + slot * H_SLOTB + (arow ^ 32) * H_ROWB + ac * 32);
        const float4 h1 = *(const float4*)(smc + OFF_H + slot * H_SLOTB + (arow ^ 32) * H_ROWB + ac * 32 + 16);
        __half2 a0 = __floats2half2_rn(m0.x - fmaxf(h0.x, 0.f), m0.y - fmaxf(h0.y, 0.f));
        __half2 a1 = __floats2half2_rn(m0.z - fmaxf(h0.z, 0.f), m0.w - fmaxf(h0.w, 0.f));
        __half2 a2 = __floats2half2_rn(m1.x - fmaxf(h1.x, 0.f), m1.y - fmaxf(h1.y, 0.f));
        __half2 a3 = __floats2half2_rn(m1.z - fmaxf(h1.z, 0.f), m1.w - fmaxf(h1.w, 0.f));
        uint4 pk;
        pk.x = *(uint32_t*)&a0; pk.y = *(uint32_t*)&a1;
        pk.z = *(uint32_t*)&a2; pk.w = *(uint32_t*)&a3;
        *(uint4*)((char*)smc + (aSt - sbase) + (kt & 1) * A_SLOTB) = pk;
    };

    const int KT = HIDDEN / BK;  // 8

    issue(0); issue(1); issue(2);
    asm volatile("cp.async.wait_group 2;\n");
    __syncthreads();
    storeA(0);

    #pragma unroll
    for (int kt = 0; kt < KT; ++kt) {
        // wait_group 1 => group kt+1 complete before storeA(kt+1)
        if (kt <= 5) asm volatile("cp.async.wait_group 1;\n");
        else         asm volatile("cp.async.wait_group 0;\n");
        __syncthreads();

        const int slot = kt % NST;

        // ---- g0 fragments first (start the LDSM chain immediately) ----
        unsigned af[2][4], bf[4][4];
        {
            const uint32_t aS = aLd0 + (kt & 1) * A_SLOTB;
            LDSM_X4(af[0][0], af[0][1], af[0][2], af[0][3], aS);
            LDSM_X4(af[1][0], af[1][1], af[1][2], af[1][3], aS + 16 * 64);
            const uint32_t bS = bLd0 + slot * B_SLOTB;
            #pragma unroll
            for (int p = 0; p < 4; ++p)
                LDSM_X4(bf[p][0], bf[p][1], bf[p][2], bf[p][3], bS + p * 16 * 64);
        }

        // independent work overlapping g0 LDSM latency
        if (kt + 1 < KT) storeA(kt + 1);

        // ---- MMA g0 ----
        #pragma unroll
        for (int mi = 0; mi < 2; ++mi) {
            #pragma unroll
            for (int p = 0; p < 4; ++p) {
                mma_f16(acc[mi][2 * p],     af[mi], &bf[p][0]);
                mma_f16(acc[mi][2 * p + 1], af[mi], &bf[p][2]);
            }
        }

        // residual: chunk kt holds cols [32kt,32kt+32) -> warp col wn == kt>>1
        if (wn == (kt >> 1)) {
            const int kl = kt & 1;
            const float* hb = (const float*)(smc + OFF_H + slot * H_SLOTB);
            #pragma unroll
            for (int mi = 0; mi < 2; ++mi) {
                const float* h0p = hb + (wm * 32 + mi * 16 + lr) * (H_ROWB / 4);
                #pragma unroll
                for (int q = 0; q < 4; ++q) {
                    const int ni = kl * 4 + q;
                    float2 v0 = *(const float2*)(h0p + q * 8 + lc * 2);
                    float2 v1 = *(const float2*)(h0p + 8 * (H_ROWB / 4) + q * 8 + lc * 2);
                    acc[mi][ni][0] += v0.x; acc[mi][ni][1] += v0.y;
                    acc[mi][ni][2] += v1.x; acc[mi][ni][3] += v1.y;
                }
            }
        }

        // ---- g1 fragments + MMA ----
        {
            const uint32_t aS = (aLd0 ^ 32) + (kt & 1) * A_SLOTB;
            LDSM_X4(af[0][0], af[0][1], af[0][2], af[0][3], aS);
            LDSM_X4(af[1][0], af[1][1], af[1][2], af[1][3], aS + 16 * 64);
            const uint32_t bS = (bLd0 ^ 32) + slot * B_SLOTB;
            #pragma unroll
            for (int p = 0; p < 4; ++p)
                LDSM_X4(bf[p][0], bf[p][1], bf[p][2], bf[p][3], bS + p * 16 * 64);
        }
        #pragma unroll
        for (int mi = 0; mi < 2; ++mi) {
            #pragma unroll
            for (int p = 0; p < 4; ++p) {
                mma_f16(acc[mi][2 * p],     af[mi], &bf[p][0]);
                mma_f16(acc[mi][2 * p + 1], af[mi], &bf[p][2]);
            }
        }

        __syncthreads();
        if (kt + 3 < KT) issue(kt + 3);
    }

    // epilogue: H_out = acc + b (residual already folded), streaming stores
    float2 bb[8];
    #pragma unroll
    for (int ni = 0; ni < 8; ++ni)
        bb[ni] = *(const float2*)(bl + wn * 64 + ni * 8 + lc * 2);

    #pragma unroll
    for (int mi = 0; mi < 2; ++mi) {
        const int r0 = wm * 32 + mi * 16 + lr;
        const int r1 = r0 + 8;
        const int ge0 = (r0 < 32) ? (e1 + r0) : (e2 + r0 - 32);
        const int ge1 = (r1 < 32) ? (e1 + r1) : (e2 + r1 - 32);
        #pragma unroll
        for (int ni = 0; ni < 8; ++ni) {
            int c0 = wn * 64 + ni * 8 + lc * 2;
            float2 o0, o1;
            o0.x = bb[ni].x + acc[mi][ni][0];
            o0.y = bb[ni].y + acc[mi][ni][1];
            o1.x = bb[ni].x + acc[mi][ni][2];
            o1.y = bb[ni].y + acc[mi][ni][3];
            __stcs((float2*)(Hout + (size_t)ge0 * HIDDEN + c0), o0);
            __stcs((float2*)(Hout + (size_t)ge1 * HIDDEN + c0), o1);
        }
    }
}

// ---------------- launch ----------------
extern "C" void kernel_launch(void* const* d_in, const int* in_sizes, int n_in,
                              void* d_out, int out_size) {
    const float* V = (const float*)d_in[0];
    const float* E = (const float*)d_in[1];
    const float* W = (const float*)d_in[2];
    const float* b = (const float*)d_in[3];
    const int* edge_index = (const int*)d_in[4];
    const int* src = edge_index;

    float* outV = (float*)d_out;
    float* outH = outV + (size_t)N_NODES * HIDDEN;

    float* gH = nullptr;
    float* gMv = nullptr;
    __half* gWh = nullptr;
    cudaGetSymbolAddress((void**)&gH, g_H);
    cudaGetSymbolAddress((void**)&gMv, g_Mv);
    cudaGetSymbolAddress((void**)&gWh, g_Wh);

    cudaFuncSetAttribute(k_gemm, cudaFuncAttributeMaxDynamicSharedMemorySize, GEMM_SMEM);

    // launches: inithist(0), scanfill(1), segsum(2), gemm(3) <- ncu captures idx 3
    k_inithist<<<81442, 256>>>(V, E, src, W);
    k_scanfill<<<98, 1024>>>(src);

    float* bufs[2] = {gH, outH};
    for (int l = 0; l < DEPTH; ++l) {
        const float* Hin = bufs[l & 1];
        float* Hout = bufs[(l + 1) & 1];
        k_segsum<true><<<12500, 256>>>(Hin, gMv);
        k_gemm<<<N_EDGES / BM, 256, GEMM_SMEM>>>(Hin, gMv, src,
                                                 gWh + (size_t)l * HIDDEN * HIDDEN,
                                                 b + (size_t)l * HIDDEN, Hout);
    }
    k_segsum<false><<<12500, 256>>>(outH, outV);
}